// round 1
// baseline (speedup 1.0000x reference)
#include <cuda_runtime.h>

// Problem constants (fixed by the reference)
#define B_ 8
#define S_ 8192
#define H_ 512
#define D_ 768
#define P_ 128

#define LCH 256          // tokens per pool block
#define HCH 256          // h-columns per pool block (== blockDim)

// Scratch (no allocations allowed)
__device__ float g_sums[B_ * P_ * H_];   // [B*P, H] segment sums
__device__ float g_cnt[B_ * P_];         // [B*P]   segment counts

// ---------------------------------------------------------------------------
// Kernel 0: zero the scratch
// ---------------------------------------------------------------------------
__global__ void zero_kernel() {
    int i = blockIdx.x * blockDim.x + threadIdx.x;
    if (i < B_ * P_ * H_) g_sums[i] = 0.0f;
    if (i < B_ * P_)      g_cnt[i]  = 0.0f;
}

// ---------------------------------------------------------------------------
// Kernel 1: run-length segment sum. Exploits sorted patch_ids:
// each thread owns one h-column over a 256-token chunk, accumulates in a
// register along each patch run, one atomicAdd per run boundary.
// grid = (S/LCH, H/HCH, B), block = HCH
// ---------------------------------------------------------------------------
__global__ void pool_kernel(const float* __restrict__ x,
                            const int*   __restrict__ pids) {
    __shared__ int sp[LCH];
    const int b  = blockIdx.z;
    const int s0 = blockIdx.x * LCH;
    const int h  = blockIdx.y * HCH + threadIdx.x;
    const int t  = threadIdx.x;

    sp[t] = pids[b * S_ + s0 + t];
    __syncthreads();

    // counts: one chunk pass (only the y==0 slice contributes)
    if (blockIdx.y == 0) {
        atomicAdd(&g_cnt[b * P_ + sp[t]], 1.0f);
    }

    const float* xp = x + ((size_t)b * S_ + s0) * H_ + h;
    float acc = 0.0f;
    int   prev = sp[0];

#pragma unroll 8
    for (int s = 0; s < LCH; ++s) {
        int p = sp[s];                       // uniform across the warp
        if (p != prev) {                     // uniform branch
            atomicAdd(&g_sums[(b * P_ + prev) * H_ + h], acc);
            acc  = 0.0f;
            prev = p;
        }
        acc += xp[(size_t)s * H_];
    }
    atomicAdd(&g_sums[(b * P_ + prev) * H_ + h], acc);
}

// ---------------------------------------------------------------------------
// Kernel 2: out[m, n] = (sums[m, :] / max(cnt[m],1)) @ W[:, n] + bias[n]
// M = B*P = 1024, K = H = 512, N = D = 768.
// 64x64 tile, BK=16, 256 threads, 4x4 micro-tile per thread.
// grid = (N/64, M/64), block = 256
// ---------------------------------------------------------------------------
#define BM 64
#define BN 64
#define BK 16

__global__ void gemm_kernel(const float* __restrict__ W,
                            const float* __restrict__ bias,
                            float* __restrict__ out) {
    __shared__ float As[BK][BM];   // A stored transposed: As[k][m]
    __shared__ float Ws[BK][BN];

    const int m0 = blockIdx.y * BM;
    const int n0 = blockIdx.x * BN;
    const int t  = threadIdx.x;          // 0..255
    const int tx = t & 15;               // 0..15 -> 4 output cols
    const int ty = t >> 4;               // 0..15 -> 4 output rows

    // A loader mapping: row lr (0..63), k-quad lk (0,4,8,12)
    const int lr = t >> 2;
    const int lk = (t & 3) * 4;
    const float  rc   = 1.0f / fmaxf(g_cnt[m0 + lr], 1.0f);
    const float* Aptr = g_sums + (size_t)(m0 + lr) * H_ + lk;

    // W loader mapping: k-row wr (0..15), n-quad wn (0,4,...,60)
    const int wr = t >> 4;
    const int wn = (t & 15) * 4;
    const float* Wptr = W + (size_t)wr * D_ + n0 + wn;

    float acc[4][4] = {};

    for (int k0 = 0; k0 < H_; k0 += BK) {
        float4 a4 = *(const float4*)(Aptr + k0);
        float4 w4 = *(const float4*)(Wptr + (size_t)k0 * D_);
        __syncthreads();                  // previous tile fully consumed
        As[lk + 0][lr] = a4.x * rc;       // scale folded into A load
        As[lk + 1][lr] = a4.y * rc;
        As[lk + 2][lr] = a4.z * rc;
        As[lk + 3][lr] = a4.w * rc;
        *(float4*)&Ws[wr][wn] = w4;
        __syncthreads();

#pragma unroll
        for (int k = 0; k < BK; ++k) {
            float4 av = *(const float4*)&As[k][ty * 4];
            float4 wv = *(const float4*)&Ws[k][tx * 4];
            float a[4] = {av.x, av.y, av.z, av.w};
            float w[4] = {wv.x, wv.y, wv.z, wv.w};
#pragma unroll
            for (int i = 0; i < 4; ++i)
#pragma unroll
                for (int j = 0; j < 4; ++j)
                    acc[i][j] += a[i] * w[j];
        }
    }

    const float4 bv = *(const float4*)(bias + n0 + tx * 4);
#pragma unroll
    for (int i = 0; i < 4; ++i) {
        const int m = m0 + ty * 4 + i;
        float4 o;
        o.x = acc[i][0] + bv.x;
        o.y = acc[i][1] + bv.y;
        o.z = acc[i][2] + bv.z;
        o.w = acc[i][3] + bv.w;
        *(float4*)(out + (size_t)m * D_ + n0 + tx * 4) = o;
    }
}

// ---------------------------------------------------------------------------
// Launch
// ---------------------------------------------------------------------------
extern "C" void kernel_launch(void* const* d_in, const int* in_sizes, int n_in,
                              void* d_out, int out_size) {
    const float* x    = (const float*)d_in[0];   // byte_hiddens [B,S,H]
    const float* W    = (const float*)d_in[1];   // W_proj [H,D]
    const float* bias = (const float*)d_in[2];   // b_proj [D]
    const int*   pids = (const int*)  d_in[3];   // patch_ids [B,S]
    float*       out  = (float*)d_out;           // [B,P,D]

    const int ztot = B_ * P_ * H_;
    zero_kernel<<<(ztot + 255) / 256, 256>>>();
    pool_kernel<<<dim3(S_ / LCH, H_ / HCH, B_), HCH>>>(x, pids);
    gemm_kernel<<<dim3(D_ / BN, (B_ * P_) / BM), 256>>>(W, bias, out);
}

// round 2
// speedup vs baseline: 1.2449x; 1.2449x over previous
#include <cuda_runtime.h>

// Problem constants (fixed by the reference)
#define B_ 8
#define S_ 8192
#define H_ 512
#define D_ 768
#define P_ 128

// Scratch (no allocations allowed)
__device__ float g_means[B_ * P_ * H_];   // [B*P, H] pooled means

// ---------------------------------------------------------------------------
// Kernel 1: segment mean via binary search (patch_ids sorted per batch row).
// One block per (patch, batch); each of 512 threads owns one h-column.
// No atomics, no scratch zeroing, counts come free from the search bounds.
// grid = (P_, B_), block = H_
// ---------------------------------------------------------------------------
__global__ void pool_kernel(const float* __restrict__ x,
                            const int*   __restrict__ pids) {
    const int b = blockIdx.y;
    const int p = blockIdx.x;
    const int h = threadIdx.x;

    const int* row = pids + (size_t)b * S_;

    // lower_bound(p): first index with row[idx] >= p
    int lo = 0, hi = S_;
    while (lo < hi) {
        int mid = (lo + hi) >> 1;
        if (row[mid] < p) lo = mid + 1; else hi = mid;
    }
    const int s0 = lo;
    // lower_bound(p+1)
    hi = S_;
    while (lo < hi) {
        int mid = (lo + hi) >> 1;
        if (row[mid] < p + 1) lo = mid + 1; else hi = mid;
    }
    const int s1 = lo;

    const float* xp = x + (size_t)b * S_ * H_ + h;
    float a0 = 0.f, a1 = 0.f, a2 = 0.f, a3 = 0.f;
    int s = s0;
    for (; s + 4 <= s1; s += 4) {            // 4 independent loads in flight
        a0 += xp[(size_t)(s + 0) * H_];
        a1 += xp[(size_t)(s + 1) * H_];
        a2 += xp[(size_t)(s + 2) * H_];
        a3 += xp[(size_t)(s + 3) * H_];
    }
    for (; s < s1; ++s) a0 += xp[(size_t)s * H_];

    const float acc = (a0 + a1) + (a2 + a3);
    const int   cnt = s1 - s0;
    const float m   = cnt ? acc * (1.0f / (float)cnt) : 0.0f;  // max(cnt,1) semantics
    g_means[((size_t)(b * P_ + p)) * H_ + h] = m;
}

// ---------------------------------------------------------------------------
// Kernel 2: out[m, n] = means[m, :] @ W[:, n] + bias[n]
// M = 1024, K = 512, N = 768. Tile 64x96, BK=16, 256 threads, 4x6 microtile.
// Grid = (768/96, 1024/64) = (8, 16) = 128 blocks -> single wave on 148 SMs.
// Per k-step per SM: 24*256/64 = 96 FFMA cyc vs 10*256 words/32 = 80 LDS cyc
// -> FFMA-bound.
// ---------------------------------------------------------------------------
#define BM 64
#define BN 96
#define BK 16
#define TM 4
#define TN 6

__global__ void gemm_kernel(const float* __restrict__ W,
                            const float* __restrict__ bias,
                            float* __restrict__ out) {
    __shared__ float As[BK][BM];   // A transposed: As[k][m]
    __shared__ float Ws[BK][BN];

    const int m0 = blockIdx.y * BM;
    const int n0 = blockIdx.x * BN;
    const int t  = threadIdx.x;          // 0..255
    const int tx = t & 15;               // 0..15 -> TN output cols
    const int ty = t >> 4;               // 0..15 -> TM output rows

    // A loader: row lr (0..63), k-quad lk (0,4,8,12); 64x16 floats per tile
    const int lr = t >> 2;
    const int lk = (t & 3) * 4;
    const float* Aptr = g_means + (size_t)(m0 + lr) * H_ + lk;

    // W loader: k-row wr (0..15), col group wn (0,6,...,90); 16x96 floats
    const int wr = t >> 4;
    const int wn = (t & 15) * 6;
    const float* Wptr = W + (size_t)wr * D_ + n0 + wn;

    float acc[TM][TN] = {};

    for (int k0 = 0; k0 < H_; k0 += BK) {
        const float4 a4 = *(const float4*)(Aptr + k0);
        const float2 w0 = *(const float2*)(Wptr + (size_t)k0 * D_ + 0);
        const float2 w1 = *(const float2*)(Wptr + (size_t)k0 * D_ + 2);
        const float2 w2 = *(const float2*)(Wptr + (size_t)k0 * D_ + 4);
        __syncthreads();                  // previous tile fully consumed
        As[lk + 0][lr] = a4.x;
        As[lk + 1][lr] = a4.y;
        As[lk + 2][lr] = a4.z;
        As[lk + 3][lr] = a4.w;
        *(float2*)&Ws[wr][wn + 0] = w0;
        *(float2*)&Ws[wr][wn + 2] = w1;
        *(float2*)&Ws[wr][wn + 4] = w2;
        __syncthreads();

#pragma unroll
        for (int k = 0; k < BK; ++k) {
            const float4 av = *(const float4*)&As[k][ty * TM];
            float a[TM] = {av.x, av.y, av.z, av.w};
            float w[TN];
            const float2 v0 = *(const float2*)&Ws[k][tx * TN + 0];
            const float2 v1 = *(const float2*)&Ws[k][tx * TN + 2];
            const float2 v2 = *(const float2*)&Ws[k][tx * TN + 4];
            w[0] = v0.x; w[1] = v0.y; w[2] = v1.x; w[3] = v1.y; w[4] = v2.x; w[5] = v2.y;
#pragma unroll
            for (int i = 0; i < TM; ++i)
#pragma unroll
                for (int j = 0; j < TN; ++j)
                    acc[i][j] += a[i] * w[j];
        }
    }

    const float2 b0 = *(const float2*)(bias + n0 + tx * TN + 0);
    const float2 b1 = *(const float2*)(bias + n0 + tx * TN + 2);
    const float2 b2 = *(const float2*)(bias + n0 + tx * TN + 4);
#pragma unroll
    for (int i = 0; i < TM; ++i) {
        float* op = out + (size_t)(m0 + ty * TM + i) * D_ + n0 + tx * TN;
        float2 o0, o1, o2;
        o0.x = acc[i][0] + b0.x;  o0.y = acc[i][1] + b0.y;
        o1.x = acc[i][2] + b1.x;  o1.y = acc[i][3] + b1.y;
        o2.x = acc[i][4] + b2.x;  o2.y = acc[i][5] + b2.y;
        *(float2*)(op + 0) = o0;
        *(float2*)(op + 2) = o1;
        *(float2*)(op + 4) = o2;
    }
}

// ---------------------------------------------------------------------------
// Launch
// ---------------------------------------------------------------------------
extern "C" void kernel_launch(void* const* d_in, const int* in_sizes, int n_in,
                              void* d_out, int out_size) {
    const float* x    = (const float*)d_in[0];   // byte_hiddens [B,S,H]
    const float* W    = (const float*)d_in[1];   // W_proj [H,D]
    const float* bias = (const float*)d_in[2];   // b_proj [D]
    const int*   pids = (const int*)  d_in[3];   // patch_ids [B,S]
    float*       out  = (float*)d_out;           // [B,P,D]

    pool_kernel<<<dim3(P_, B_), H_>>>(x, pids);
    gemm_kernel<<<dim3(D_ / BN, (B_ * P_) / BM), 256>>>(W, bias, out);
}

// round 3
// speedup vs baseline: 1.4995x; 1.2046x over previous
#include <cuda_runtime.h>

// Problem constants (fixed by the reference)
#define B_ 8
#define S_ 8192
#define H_ 512
#define D_ 768
#define P_ 128

// Scratch (no allocations allowed)
__device__ float g_means[B_ * P_ * H_];   // [B*P, H] pooled means

// ---------------------------------------------------------------------------
// Kernel 1: segment mean via binary search (patch_ids sorted per batch row).
// One block per (patch, batch); 128 threads, each owns 4 h-columns (float4).
// 8-deep unroll -> 8 outstanding 16B loads per thread (128B in flight).
// grid = (P_, B_), block = 128
// ---------------------------------------------------------------------------
__global__ void pool_kernel(const float* __restrict__ x,
                            const int*   __restrict__ pids) {
    const int b = blockIdx.y;
    const int p = blockIdx.x;
    const int t = threadIdx.x;           // 0..127 -> float4 column

    const int* row = pids + (size_t)b * S_;

    // lower_bound(p)
    int lo = 0, hi = S_;
    while (lo < hi) {
        int mid = (lo + hi) >> 1;
        if (row[mid] < p) lo = mid + 1; else hi = mid;
    }
    const int s0 = lo;
    // lower_bound(p+1)
    hi = S_;
    while (lo < hi) {
        int mid = (lo + hi) >> 1;
        if (row[mid] < p + 1) lo = mid + 1; else hi = mid;
    }
    const int s1 = lo;

    const float4* xp = (const float4*)x + (size_t)b * S_ * (H_ / 4) + t;

    float4 a[8];
#pragma unroll
    for (int i = 0; i < 8; ++i) a[i] = make_float4(0.f, 0.f, 0.f, 0.f);

    int s = s0;
    for (; s + 8 <= s1; s += 8) {
#pragma unroll
        for (int i = 0; i < 8; ++i) {
            const float4 v = xp[(size_t)(s + i) * (H_ / 4)];
            a[i].x += v.x; a[i].y += v.y; a[i].z += v.z; a[i].w += v.w;
        }
    }
    for (; s < s1; ++s) {
        const float4 v = xp[(size_t)s * (H_ / 4)];
        a[0].x += v.x; a[0].y += v.y; a[0].z += v.z; a[0].w += v.w;
    }

    // pairwise reduce 8 accumulators
#pragma unroll
    for (int i = 0; i < 4; ++i) {
        a[i].x += a[i + 4].x; a[i].y += a[i + 4].y;
        a[i].z += a[i + 4].z; a[i].w += a[i + 4].w;
    }
    a[0].x += a[2].x; a[0].y += a[2].y; a[0].z += a[2].z; a[0].w += a[2].w;
    a[1].x += a[3].x; a[1].y += a[3].y; a[1].z += a[3].z; a[1].w += a[3].w;
    float4 acc;
    acc.x = a[0].x + a[1].x; acc.y = a[0].y + a[1].y;
    acc.z = a[0].z + a[1].z; acc.w = a[0].w + a[1].w;

    const int   cnt = s1 - s0;
    const float rc  = cnt ? (1.0f / (float)cnt) : 0.0f;   // max(cnt,1): empty -> 0
    float4 m = make_float4(acc.x * rc, acc.y * rc, acc.z * rc, acc.w * rc);

    ((float4*)g_means)[(size_t)(b * P_ + p) * (H_ / 4) + t] = m;
}

// ---------------------------------------------------------------------------
// Kernel 2: out = means @ W + bias. M=1024, K=512, N=768.
// 64x96 tile, BK=16, 256 threads, 4x6 microtile, DOUBLE-BUFFERED smem with
// register-staged prefetch; one __syncthreads per BK iteration.
// grid = (8, 16) = 128 blocks -> single wave.
// ---------------------------------------------------------------------------
#define BM 64
#define BN 96
#define BK 16
#define TM 4
#define TN 6

__global__ void gemm_kernel(const float* __restrict__ W,
                            const float* __restrict__ bias,
                            float* __restrict__ out) {
    __shared__ float As[2][BK][BM];   // A transposed: As[buf][k][m]
    __shared__ float Ws[2][BK][BN];

    const int m0 = blockIdx.y * BM;
    const int n0 = blockIdx.x * BN;
    const int t  = threadIdx.x;          // 0..255
    const int tx = t & 15;               // TN output cols
    const int ty = t >> 4;               // TM output rows

    // A loader: row lr (0..63), k-quad lk (0,4,8,12)
    const int lr = t >> 2;
    const int lk = (t & 3) * 4;
    const float* Aptr = g_means + (size_t)(m0 + lr) * H_ + lk;

    // W loader: k-row wr (0..15), col group wn (0,6,...,90)
    const int wr = t >> 4;
    const int wn = (t & 15) * 6;
    const float* Wptr = W + (size_t)wr * D_ + n0 + wn;

    float acc[TM][TN] = {};

    // ---- prologue: tile 0 into buffer 0
    float4 a4 = *(const float4*)(Aptr);
    float2 w0 = *(const float2*)(Wptr + 0);
    float2 w1 = *(const float2*)(Wptr + 2);
    float2 w2 = *(const float2*)(Wptr + 4);
    As[0][lk + 0][lr] = a4.x;
    As[0][lk + 1][lr] = a4.y;
    As[0][lk + 2][lr] = a4.z;
    As[0][lk + 3][lr] = a4.w;
    *(float2*)&Ws[0][wr][wn + 0] = w0;
    *(float2*)&Ws[0][wr][wn + 2] = w1;
    *(float2*)&Ws[0][wr][wn + 4] = w2;
    __syncthreads();

    int cur = 0;
    for (int k0 = BK; k0 <= H_; k0 += BK) {
        const bool more = (k0 < H_);
        if (more) {   // prefetch next tile into registers (latency hidden by compute)
            a4 = *(const float4*)(Aptr + k0);
            w0 = *(const float2*)(Wptr + (size_t)k0 * D_ + 0);
            w1 = *(const float2*)(Wptr + (size_t)k0 * D_ + 2);
            w2 = *(const float2*)(Wptr + (size_t)k0 * D_ + 4);
        }

#pragma unroll
        for (int k = 0; k < BK; ++k) {
            const float4 av = *(const float4*)&As[cur][k][ty * TM];
            const float2 v0 = *(const float2*)&Ws[cur][k][tx * TN + 0];
            const float2 v1 = *(const float2*)&Ws[cur][k][tx * TN + 2];
            const float2 v2 = *(const float2*)&Ws[cur][k][tx * TN + 4];
            const float a[TM] = {av.x, av.y, av.z, av.w};
            const float w[TN] = {v0.x, v0.y, v1.x, v1.y, v2.x, v2.y};
#pragma unroll
            for (int i = 0; i < TM; ++i)
#pragma unroll
                for (int j = 0; j < TN; ++j)
                    acc[i][j] += a[i] * w[j];
        }

        if (more) {
            const int nxt = cur ^ 1;      // write buffer nobody is reading
            As[nxt][lk + 0][lr] = a4.x;
            As[nxt][lk + 1][lr] = a4.y;
            As[nxt][lk + 2][lr] = a4.z;
            As[nxt][lk + 3][lr] = a4.w;
            *(float2*)&Ws[nxt][wr][wn + 0] = w0;
            *(float2*)&Ws[nxt][wr][wn + 2] = w1;
            *(float2*)&Ws[nxt][wr][wn + 4] = w2;
            __syncthreads();              // single sync per iteration
            cur = nxt;
        }
    }

    const float2 b0 = *(const float2*)(bias + n0 + tx * TN + 0);
    const float2 b1 = *(const float2*)(bias + n0 + tx * TN + 2);
    const float2 b2 = *(const float2*)(bias + n0 + tx * TN + 4);
#pragma unroll
    for (int i = 0; i < TM; ++i) {
        float* op = out + (size_t)(m0 + ty * TM + i) * D_ + n0 + tx * TN;
        float2 o0, o1, o2;
        o0.x = acc[i][0] + b0.x;  o0.y = acc[i][1] + b0.y;
        o1.x = acc[i][2] + b1.x;  o1.y = acc[i][3] + b1.y;
        o2.x = acc[i][4] + b2.x;  o2.y = acc[i][5] + b2.y;
        *(float2*)(op + 0) = o0;
        *(float2*)(op + 2) = o1;
        *(float2*)(op + 4) = o2;
    }
}

// ---------------------------------------------------------------------------
// Launch
// ---------------------------------------------------------------------------
extern "C" void kernel_launch(void* const* d_in, const int* in_sizes, int n_in,
                              void* d_out, int out_size) {
    const float* x    = (const float*)d_in[0];   // byte_hiddens [B,S,H]
    const float* W    = (const float*)d_in[1];   // W_proj [H,D]
    const float* bias = (const float*)d_in[2];   // b_proj [D]
    const int*   pids = (const int*)  d_in[3];   // patch_ids [B,S]
    float*       out  = (float*)d_out;           // [B,P,D]

    pool_kernel<<<dim3(P_, B_), 128>>>(x, pids);
    gemm_kernel<<<dim3(D_ / BN, (B_ * P_) / BM), 256>>>(W, bias, out);
}

// round 4
// speedup vs baseline: 1.8091x; 1.2064x over previous
#include <cuda_runtime.h>
#include <cstdint>

// Problem constants (fixed by the reference)
#define B_ 8
#define S_ 8192
#define H_ 512
#define D_ 768
#define P_ 128

// Scratch (no allocations allowed)
__device__ float g_means[B_ * P_ * H_];     // [B*P, H] pooled means
__device__ int   g_off[B_ * (P_ + 1)];      // patch start offsets per batch row

// ---------------------------------------------------------------------------
// Kernel 0: patch boundary offsets from sorted patch_ids.
// g_off[b][p] = first s with pids[b][s] >= p ; g_off[b][P] = S.
// One thread per token; writes only at run boundaries (~1K scalar writes).
// ---------------------------------------------------------------------------
__global__ void offsets_kernel(const int* __restrict__ pids) {
    const int idx = blockIdx.x * blockDim.x + threadIdx.x;   // 0 .. B*S-1
    if (idx >= B_ * S_) return;
    const int b = idx / S_;
    const int s = idx - b * S_;
    const int cur  = pids[idx];
    const int prev = (s == 0) ? -1 : pids[idx - 1];
    for (int p = prev + 1; p <= cur; ++p)
        g_off[b * (P_ + 1) + p] = s;
    if (s == S_ - 1)
        for (int p = cur + 1; p <= P_; ++p)
            g_off[b * (P_ + 1) + p] = S_;
}

// ---------------------------------------------------------------------------
// Kernel 1: segment mean. One block per (patch, batch); 128 threads, each
// owns 4 h-columns (float4), 8-deep unroll. Range comes from g_off (no search).
// grid = (P_, B_), block = 128
// ---------------------------------------------------------------------------
__global__ void pool_kernel(const float* __restrict__ x) {
    const int b = blockIdx.y;
    const int p = blockIdx.x;
    const int t = threadIdx.x;           // 0..127 -> float4 column

    const int s0 = g_off[b * (P_ + 1) + p];
    const int s1 = g_off[b * (P_ + 1) + p + 1];

    const float4* xp = (const float4*)x + (size_t)b * S_ * (H_ / 4) + t;

    float4 a[8];
#pragma unroll
    for (int i = 0; i < 8; ++i) a[i] = make_float4(0.f, 0.f, 0.f, 0.f);

    int s = s0;
    for (; s + 8 <= s1; s += 8) {
#pragma unroll
        for (int i = 0; i < 8; ++i) {
            const float4 v = xp[(size_t)(s + i) * (H_ / 4)];
            a[i].x += v.x; a[i].y += v.y; a[i].z += v.z; a[i].w += v.w;
        }
    }
    for (; s < s1; ++s) {
        const float4 v = xp[(size_t)s * (H_ / 4)];
        a[0].x += v.x; a[0].y += v.y; a[0].z += v.z; a[0].w += v.w;
    }

#pragma unroll
    for (int i = 0; i < 4; ++i) {
        a[i].x += a[i + 4].x; a[i].y += a[i + 4].y;
        a[i].z += a[i + 4].z; a[i].w += a[i + 4].w;
    }
    a[0].x += a[2].x; a[0].y += a[2].y; a[0].z += a[2].z; a[0].w += a[2].w;
    a[1].x += a[3].x; a[1].y += a[3].y; a[1].z += a[3].z; a[1].w += a[3].w;

    const int   cnt = s1 - s0;
    const float rc  = cnt ? (1.0f / (float)cnt) : 0.0f;    // max(cnt,1) semantics
    float4 m;
    m.x = (a[0].x + a[1].x) * rc;
    m.y = (a[0].y + a[1].y) * rc;
    m.z = (a[0].z + a[1].z) * rc;
    m.w = (a[0].w + a[1].w) * rc;

    ((float4*)g_means)[(size_t)(b * P_ + p) * (H_ / 4) + t] = m;
}

// ---------------------------------------------------------------------------
// Kernel 2: out = means @ W + bias via tf32 tensor cores with 3-product
// Markidis split (fp32-equivalent accuracy).
// M=1024, K=512, N=768. Block tile 64x96, BK=16, 256 threads (8 warps),
// warp grid 2(m) x 4(n), warp tile 32x24 = 2 m16-frags x 3 n8-frags.
// Double-buffered smem, register prefetch, one sync/iter.
// grid = (8, 16) = 128 blocks -> single wave.
// ---------------------------------------------------------------------------
#define BM 64
#define BN 96
#define BK 16

__device__ __forceinline__ void tf32_split(float v, uint32_t& hi, uint32_t& lo) {
    asm("cvt.rna.tf32.f32 %0, %1;" : "=r"(hi) : "f"(v));
    const float r = v - __uint_as_float(hi);
    asm("cvt.rna.tf32.f32 %0, %1;" : "=r"(lo) : "f"(r));
}

__device__ __forceinline__ void mma_tf32(float* c, const uint32_t* a,
                                         uint32_t b0, uint32_t b1) {
    asm volatile(
        "mma.sync.aligned.m16n8k8.row.col.f32.tf32.tf32.f32 "
        "{%0,%1,%2,%3}, {%4,%5,%6,%7}, {%8,%9}, {%0,%1,%2,%3};"
        : "+f"(c[0]), "+f"(c[1]), "+f"(c[2]), "+f"(c[3])
        : "r"(a[0]), "r"(a[1]), "r"(a[2]), "r"(a[3]), "r"(b0), "r"(b1));
}

__global__ __launch_bounds__(256, 1)
void gemm_kernel(const float* __restrict__ W,
                 const float* __restrict__ bias,
                 float* __restrict__ out) {
    __shared__ float As[2][BM][20];    // [m][k], k padded 16->20 (conflict-free frags)
    __shared__ float Ws[2][BK][104];   // [k][n], n padded 96->104 (conflict-free frags)

    const int m0 = blockIdx.y * BM;
    const int n0 = blockIdx.x * BN;
    const int t  = threadIdx.x;          // 0..255
    const int w  = t >> 5;               // warp 0..7
    const int ln = t & 31;               // lane
    const int g  = ln >> 2;              // groupID 0..7
    const int tg = ln & 3;               // threadID_in_group 0..3
    const int wm = w & 1;                // warp m index (0..1) -> 32 rows
    const int wn = w >> 1;               // warp n index (0..3) -> 24 cols

    // A loader: row lr (0..63), k-quad lk
    const int lr = t >> 2;
    const int lk = (t & 3) * 4;
    const float* Aptr = g_means + (size_t)(m0 + lr) * H_ + lk;

    // W loader: k-row wr (0..15), col group wcn (0,6,...,90)
    const int wr  = t >> 4;
    const int wcn = (t & 15) * 6;
    const float* Wptr = W + (size_t)wr * D_ + n0 + wcn;

    float acc[2][3][4] = {};             // [mf][nf][c0..c3]

    // ---- prologue: tile 0 -> buffer 0
    float4 a4 = *(const float4*)(Aptr);
    float2 w0 = *(const float2*)(Wptr + 0);
    float2 w1 = *(const float2*)(Wptr + 2);
    float2 w2 = *(const float2*)(Wptr + 4);
    *(float4*)&As[0][lr][lk] = a4;
    Ws[0][wr][wcn + 0] = w0.x; Ws[0][wr][wcn + 1] = w0.y;
    Ws[0][wr][wcn + 2] = w1.x; Ws[0][wr][wcn + 3] = w1.y;
    Ws[0][wr][wcn + 4] = w2.x; Ws[0][wr][wcn + 5] = w2.y;
    __syncthreads();

    int cur = 0;
    for (int k0 = BK; k0 <= H_; k0 += BK) {
        const bool more = (k0 < H_);
        if (more) {
            a4 = *(const float4*)(Aptr + k0);
            w0 = *(const float2*)(Wptr + (size_t)k0 * D_ + 0);
            w1 = *(const float2*)(Wptr + (size_t)k0 * D_ + 2);
            w2 = *(const float2*)(Wptr + (size_t)k0 * D_ + 4);
        }

#pragma unroll
        for (int ks = 0; ks < BK; ks += 8) {
            // A fragments (2 m16-frags), split hi/lo
            uint32_t Ahi[2][4], Alo[2][4];
#pragma unroll
            for (int mf = 0; mf < 2; ++mf) {
                const int r = wm * 32 + mf * 16 + g;
                const int c = ks + tg;
                tf32_split(As[cur][r][c],         Ahi[mf][0], Alo[mf][0]);
                tf32_split(As[cur][r + 8][c],     Ahi[mf][1], Alo[mf][1]);
                tf32_split(As[cur][r][c + 4],     Ahi[mf][2], Alo[mf][2]);
                tf32_split(As[cur][r + 8][c + 4], Ahi[mf][3], Alo[mf][3]);
            }
#pragma unroll
            for (int nf = 0; nf < 3; ++nf) {
                const int n = wn * 24 + nf * 8 + g;
                const int k = ks + tg;
                uint32_t Bhi0, Blo0, Bhi1, Blo1;
                tf32_split(Ws[cur][k][n],     Bhi0, Blo0);
                tf32_split(Ws[cur][k + 4][n], Bhi1, Blo1);
#pragma unroll
                for (int mf = 0; mf < 2; ++mf) {
                    mma_tf32(acc[mf][nf], Ahi[mf], Bhi0, Bhi1);  // hi*hi
                    mma_tf32(acc[mf][nf], Alo[mf], Bhi0, Bhi1);  // lo*hi
                    mma_tf32(acc[mf][nf], Ahi[mf], Blo0, Blo1);  // hi*lo
                }
            }
        }

        if (more) {
            const int nxt = cur ^ 1;
            *(float4*)&As[nxt][lr][lk] = a4;
            Ws[nxt][wr][wcn + 0] = w0.x; Ws[nxt][wr][wcn + 1] = w0.y;
            Ws[nxt][wr][wcn + 2] = w1.x; Ws[nxt][wr][wcn + 3] = w1.y;
            Ws[nxt][wr][wcn + 4] = w2.x; Ws[nxt][wr][wcn + 5] = w2.y;
            __syncthreads();
            cur = nxt;
        }
    }

    // ---- epilogue: c0:(g, 2tg) c1:(g, 2tg+1) c2:(g+8, 2tg) c3:(g+8, 2tg+1)
#pragma unroll
    for (int nf = 0; nf < 3; ++nf) {
        const int ncol = n0 + wn * 24 + nf * 8 + 2 * tg;
        const float2 bv = *(const float2*)(bias + ncol);
#pragma unroll
        for (int mf = 0; mf < 2; ++mf) {
            const int mrow = m0 + wm * 32 + mf * 16 + g;
            float2 o0, o1;
            o0.x = acc[mf][nf][0] + bv.x;  o0.y = acc[mf][nf][1] + bv.y;
            o1.x = acc[mf][nf][2] + bv.x;  o1.y = acc[mf][nf][3] + bv.y;
            *(float2*)(out + (size_t)mrow * D_ + ncol)       = o0;
            *(float2*)(out + (size_t)(mrow + 8) * D_ + ncol) = o1;
        }
    }
}

// ---------------------------------------------------------------------------
// Launch
// ---------------------------------------------------------------------------
extern "C" void kernel_launch(void* const* d_in, const int* in_sizes, int n_in,
                              void* d_out, int out_size) {
    const float* x    = (const float*)d_in[0];   // byte_hiddens [B,S,H]
    const float* W    = (const float*)d_in[1];   // W_proj [H,D]
    const float* bias = (const float*)d_in[2];   // b_proj [D]
    const int*   pids = (const int*)  d_in[3];   // patch_ids [B,S]
    float*       out  = (float*)d_out;           // [B,P,D]

    offsets_kernel<<<(B_ * S_ + 255) / 256, 256>>>(pids);
    pool_kernel<<<dim3(P_, B_), 128>>>(x);
    gemm_kernel<<<dim3(D_ / BN, (B_ * P_) / BM), 256>>>(W, bias, out);
}

// round 5
// speedup vs baseline: 2.0279x; 1.1210x over previous
#include <cuda_runtime.h>
#include <cuda_bf16.h>
#include <cstdint>

// Problem constants (fixed by the reference)
#define B_ 8
#define S_ 8192
#define H_ 512
#define D_ 768
#define P_ 128

// Scratch (no allocations allowed)
__device__ float g_means[B_ * P_ * H_];     // [B*P, H] pooled means

// ---------------------------------------------------------------------------
// Kernel 1: segment mean via binary search (patch_ids sorted per batch row).
// grid = (P_, B_, 2) ; block = 64 threads, each owns one float4 h-column.
// z splits the h range -> 2048 blocks for better tail/overlap.
// ---------------------------------------------------------------------------
__global__ void pool_kernel(const float* __restrict__ x,
                            const int*   __restrict__ pids) {
    const int b  = blockIdx.y;
    const int p  = blockIdx.x;
    const int hq = blockIdx.z * 64 + threadIdx.x;   // float4 column 0..127

    const int* row = pids + (size_t)b * S_;

    // lower_bound(p)
    int lo = 0, hi = S_;
    while (lo < hi) {
        int mid = (lo + hi) >> 1;
        if (__ldg(row + mid) < p) lo = mid + 1; else hi = mid;
    }
    const int s0 = lo;
    // lower_bound(p+1)
    hi = S_;
    while (lo < hi) {
        int mid = (lo + hi) >> 1;
        if (__ldg(row + mid) < p + 1) lo = mid + 1; else hi = mid;
    }
    const int s1 = lo;

    const float4* xp = (const float4*)x + (size_t)b * S_ * (H_ / 4) + hq;

    float4 a[8];
#pragma unroll
    for (int i = 0; i < 8; ++i) a[i] = make_float4(0.f, 0.f, 0.f, 0.f);

    int s = s0;
    for (; s + 8 <= s1; s += 8) {
#pragma unroll
        for (int i = 0; i < 8; ++i) {
            const float4 v = __ldcs(&xp[(size_t)(s + i) * (H_ / 4)]);
            a[i].x += v.x; a[i].y += v.y; a[i].z += v.z; a[i].w += v.w;
        }
    }
    for (; s < s1; ++s) {
        const float4 v = __ldcs(&xp[(size_t)s * (H_ / 4)]);
        a[0].x += v.x; a[0].y += v.y; a[0].z += v.z; a[0].w += v.w;
    }

#pragma unroll
    for (int i = 0; i < 4; ++i) {
        a[i].x += a[i + 4].x; a[i].y += a[i + 4].y;
        a[i].z += a[i + 4].z; a[i].w += a[i + 4].w;
    }
    a[0].x += a[2].x; a[0].y += a[2].y; a[0].z += a[2].z; a[0].w += a[2].w;
    a[1].x += a[3].x; a[1].y += a[3].y; a[1].z += a[3].z; a[1].w += a[3].w;

    const int   cnt = s1 - s0;
    const float rc  = cnt ? (1.0f / (float)cnt) : 0.0f;   // max(cnt,1) semantics
    float4 m;
    m.x = (a[0].x + a[1].x) * rc;
    m.y = (a[0].y + a[1].y) * rc;
    m.z = (a[0].z + a[1].z) * rc;
    m.w = (a[0].w + a[1].w) * rc;

    ((float4*)g_means)[(size_t)(b * P_ + p) * (H_ / 4) + hq] = m;
}

// ---------------------------------------------------------------------------
// Kernel 2: out = means @ W + bias via bf16 tensor cores, 3-product split
// (hi*hi + lo*hi + hi*lo; missing lo*lo term ~2^-18 -> rel_err ~1e-5).
// hi/lo split + bf16x2 packing done ONCE at smem-store time.
// M=1024, K=512, N=768. Block 64x96, BK=16 (one m16n8k16 slab per iter),
// 256 threads (8 warps: 2m x 4n), warp tile 32x24 (2 mf x 3 nf frags).
// Double-buffered, register prefetch, one sync/iter. grid=(8,16)=128 blocks.
// ---------------------------------------------------------------------------
#define BM 64
#define BN 96
#define BK 16

__device__ __forceinline__ uint32_t bf16pack(float lo_elem, float hi_elem) {
    // low 16 bits = lo_elem (even k), high 16 bits = hi_elem (odd k)
    uint32_t r;
    asm("cvt.rn.bf16x2.f32 %0, %1, %2;" : "=r"(r) : "f"(hi_elem), "f"(lo_elem));
    return r;
}

__device__ __forceinline__ void bsplit(float v, float& h, float& l) {
    h = __bfloat162float(__float2bfloat16_rn(v));
    l = v - h;
}

__device__ __forceinline__ void mma_bf16(float* c, const uint32_t* a,
                                         uint32_t b0, uint32_t b1) {
    asm volatile(
        "mma.sync.aligned.m16n8k16.row.col.f32.bf16.bf16.f32 "
        "{%0,%1,%2,%3}, {%4,%5,%6,%7}, {%8,%9}, {%0,%1,%2,%3};"
        : "+f"(c[0]), "+f"(c[1]), "+f"(c[2]), "+f"(c[3])
        : "r"(a[0]), "r"(a[1]), "r"(a[2]), "r"(a[3]), "r"(b0), "r"(b1));
}

__global__ __launch_bounds__(256, 1)
void gemm_kernel(const float* __restrict__ W,
                 const float* __restrict__ bias,
                 float* __restrict__ out) {
    // A: [m][k2] packed bf16x2, k2 = 0..7, padded stride 12 (conflict-free frags)
    __shared__ uint32_t Ah[2][BM][12];
    __shared__ uint32_t Al[2][BM][12];
    // W: [k2][n] packed bf16x2 (k-pairs), n padded 96 -> 104 (conflict-free)
    __shared__ uint32_t Wh[2][8][104];
    __shared__ uint32_t Wl[2][8][104];

    const int m0 = blockIdx.y * BM;
    const int n0 = blockIdx.x * BN;
    const int t  = threadIdx.x;          // 0..255
    const int w  = t >> 5;               // warp 0..7
    const int ln = t & 31;
    const int g  = ln >> 2;              // groupID 0..7
    const int tg = ln & 3;               // threadID_in_group 0..3
    const int wm = w & 1;                // warp m (0..1) -> 32 rows
    const int wn = w >> 1;               // warp n (0..3) -> 24 cols

    // A loader: row lr (0..63), k-quad lk (0,4,8,12), packed index lk2
    const int lr  = t >> 2;
    const int lk  = (t & 3) * 4;
    const int lk2 = (t & 3) * 2;
    const float* Aptr = g_means + (size_t)(m0 + lr) * H_ + lk;

    // W loader: k-pair k2w (0..7), col base nb (0,3,...,93)
    const int k2w = t >> 5;
    const int nb  = (t & 31) * 3;
    const float* Wp0 = W + (size_t)(2 * k2w) * D_ + n0 + nb;   // even k row
    const float* Wp1 = Wp0 + D_;                               // odd k row

    float acc[2][3][4] = {};             // [mf][nf][c0..c3]

    float4 a4;
    float  wv0[3], wv1[3];

    // ---- prologue: tile 0 -> buffer 0
    a4 = *(const float4*)(Aptr);
#pragma unroll
    for (int j = 0; j < 3; ++j) { wv0[j] = Wp0[j]; wv1[j] = Wp1[j]; }
    {
        float h0,l0,h1,l1,h2,l2,h3,l3;
        bsplit(a4.x,h0,l0); bsplit(a4.y,h1,l1);
        bsplit(a4.z,h2,l2); bsplit(a4.w,h3,l3);
        Ah[0][lr][lk2]     = bf16pack(h0, h1);
        Ah[0][lr][lk2 + 1] = bf16pack(h2, h3);
        Al[0][lr][lk2]     = bf16pack(l0, l1);
        Al[0][lr][lk2 + 1] = bf16pack(l2, l3);
#pragma unroll
        for (int j = 0; j < 3; ++j) {
            float ha,la,hb,lb;
            bsplit(wv0[j], ha, la); bsplit(wv1[j], hb, lb);
            Wh[0][k2w][nb + j] = bf16pack(ha, hb);   // low = even k
            Wl[0][k2w][nb + j] = bf16pack(la, lb);
        }
    }
    __syncthreads();

    int cur = 0;
    for (int k0 = BK; k0 <= H_; k0 += BK) {
        const bool more = (k0 < H_);
        if (more) {
            a4 = *(const float4*)(Aptr + k0);
            const float* p0 = Wp0 + (size_t)k0 * D_;
            const float* p1 = Wp1 + (size_t)k0 * D_;
#pragma unroll
            for (int j = 0; j < 3; ++j) { wv0[j] = p0[j]; wv1[j] = p1[j]; }
        }

        // ---- compute on buffer cur (one m16n8k16 slab)
        uint32_t ah[2][4], al[2][4];
#pragma unroll
        for (int mf = 0; mf < 2; ++mf) {
            const int r = wm * 32 + mf * 16 + g;
            ah[mf][0] = Ah[cur][r][tg];         al[mf][0] = Al[cur][r][tg];
            ah[mf][1] = Ah[cur][r + 8][tg];     al[mf][1] = Al[cur][r + 8][tg];
            ah[mf][2] = Ah[cur][r][tg + 4];     al[mf][2] = Al[cur][r][tg + 4];
            ah[mf][3] = Ah[cur][r + 8][tg + 4]; al[mf][3] = Al[cur][r + 8][tg + 4];
        }
#pragma unroll
        for (int nf = 0; nf < 3; ++nf) {
            const int n = wn * 24 + nf * 8 + g;
            const uint32_t bh0 = Wh[cur][tg][n],     bh1 = Wh[cur][tg + 4][n];
            const uint32_t bl0 = Wl[cur][tg][n],     bl1 = Wl[cur][tg + 4][n];
#pragma unroll
            for (int mf = 0; mf < 2; ++mf) {
                mma_bf16(acc[mf][nf], ah[mf], bh0, bh1);   // hi*hi
                mma_bf16(acc[mf][nf], al[mf], bh0, bh1);   // lo*hi
                mma_bf16(acc[mf][nf], ah[mf], bl0, bl1);   // hi*lo
            }
        }

        if (more) {
            const int nxt = cur ^ 1;
            float h0,l0,h1,l1,h2,l2,h3,l3;
            bsplit(a4.x,h0,l0); bsplit(a4.y,h1,l1);
            bsplit(a4.z,h2,l2); bsplit(a4.w,h3,l3);
            Ah[nxt][lr][lk2]     = bf16pack(h0, h1);
            Ah[nxt][lr][lk2 + 1] = bf16pack(h2, h3);
            Al[nxt][lr][lk2]     = bf16pack(l0, l1);
            Al[nxt][lr][lk2 + 1] = bf16pack(l2, l3);
#pragma unroll
            for (int j = 0; j < 3; ++j) {
                float ha,la,hb,lb;
                bsplit(wv0[j], ha, la); bsplit(wv1[j], hb, lb);
                Wh[nxt][k2w][nb + j] = bf16pack(ha, hb);
                Wl[nxt][k2w][nb + j] = bf16pack(la, lb);
            }
            __syncthreads();
            cur = nxt;
        }
    }

    // ---- epilogue: c0,c1 = row g cols 2tg,2tg+1 ; c2,c3 = row g+8
#pragma unroll
    for (int nf = 0; nf < 3; ++nf) {
        const int ncol = n0 + wn * 24 + nf * 8 + 2 * tg;
        const float2 bv = *(const float2*)(bias + ncol);
#pragma unroll
        for (int mf = 0; mf < 2; ++mf) {
            const int mrow = m0 + wm * 32 + mf * 16 + g;
            float2 o0, o1;
            o0.x = acc[mf][nf][0] + bv.x;  o0.y = acc[mf][nf][1] + bv.y;
            o1.x = acc[mf][nf][2] + bv.x;  o1.y = acc[mf][nf][3] + bv.y;
            *(float2*)(out + (size_t)mrow * D_ + ncol)       = o0;
            *(float2*)(out + (size_t)(mrow + 8) * D_ + ncol) = o1;
        }
    }
}

// ---------------------------------------------------------------------------
// Launch
// ---------------------------------------------------------------------------
extern "C" void kernel_launch(void* const* d_in, const int* in_sizes, int n_in,
                              void* d_out, int out_size) {
    const float* x    = (const float*)d_in[0];   // byte_hiddens [B,S,H]
    const float* W    = (const float*)d_in[1];   // W_proj [H,D]
    const float* bias = (const float*)d_in[2];   // b_proj [D]
    const int*   pids = (const int*)  d_in[3];   // patch_ids [B,S]
    float*       out  = (float*)d_out;           // [B,P,D]

    pool_kernel<<<dim3(P_, B_, 2), 64>>>(x, pids);
    gemm_kernel<<<dim3(D_ / BN, (B_ * P_) / BM), 256>>>(W, bias, out);
}